// round 10
// baseline (speedup 1.0000x reference)
#include <cuda_runtime.h>
#include <cuda_fp16.h>
#include <math.h>
#include <mma.h>

using namespace nvcuda;

#define NN 50000
#define EE 800000
#define ETOT (EE + NN)
#define BB 64
#define F_IN 128
#define POS 16
#define ENH 144
#define HC 256
#define OUT_DIM 128
#define SCAN_B 1024
#define NBLK ((NN + SCAN_B - 1) / SCAN_B)   // 49

// ---------------- scratch (device globals; no allocation allowed) ----------------
__device__ __half g_hH[(size_t)NN * HC];    // GEMM output (feeds aggregation only)
__device__ float  g_hF[(size_t)NN * HC];    // agg output (feeds BN-fused GEMM2 / pool)
__device__ float g_as[NN * 4];
__device__ float g_ad[NN * 4];
__device__ int   g_deg[NN];
__device__ int   g_off[NN + 1];
__device__ int   g_cur[NN];
__device__ int   g_csr[ETOT];
__device__ int   g_bsum[NBLK];
__device__ int   g_counts[BB];
__device__ int   g_starts[BB];
__device__ int   g_gs[BB];
__device__ float g_bn1[512];
__device__ float g_bn2[512];
__device__ float g_pool[BB * HC];

// ---------------- side stream + events (host-side resources, created once) -------
static cudaStream_t g_s2 = nullptr;
static cudaEvent_t  g_evFork = nullptr, g_evJoin = nullptr;
static struct StreamInit {
    StreamInit() {
        cudaStreamCreateWithFlags(&g_s2, cudaStreamNonBlocking);
        cudaEventCreateWithFlags(&g_evFork, cudaEventDisableTiming);
        cudaEventCreateWithFlags(&g_evJoin, cudaEventDisableTiming);
    }
} g_streamInit;

// ---------------- zero scratch ----------------
__global__ void k_zero() {
    int stride = gridDim.x * blockDim.x;
    int i = blockIdx.x * blockDim.x + threadIdx.x;
    for (int j = i; j < NN; j += stride) g_deg[j] = 0;
    for (int j = i; j < BB; j += stride) g_counts[j] = 0;
    for (int j = i; j < 512; j += stride) { g_bn1[j] = 0.f; g_bn2[j] = 0.f; }
    for (int j = i; j < BB * HC; j += stride) g_pool[j] = 0.f;
}

// ---------------- graph counts ----------------
__global__ void k_counts(const int* __restrict__ batch) {
    __shared__ int sm[BB];
    int t = threadIdx.x;
    if (t < BB) sm[t] = 0;
    __syncthreads();
    int i = blockIdx.x * blockDim.x + t;
    if (i < NN) atomicAdd(&sm[batch[i]], 1);
    __syncthreads();
    if (t < BB && sm[t]) atomicAdd(&g_counts[t], sm[t]);
}

__global__ void k_graph_meta() {
    if (threadIdx.x == 0 && blockIdx.x == 0) {
        int acc = 0;
        for (int b = 0; b < BB; b++) {
            int c = g_counts[b];
            g_starts[b] = acc;
            acc += c;
            g_gs[b] = (int)ceilf(sqrtf((float)c));
        }
    }
}

// ---------------- CSR build ----------------
__global__ void k_degree(const int* __restrict__ ei) {
    int e = blockIdx.x * blockDim.x + threadIdx.x;
    if (e >= ETOT) return;
    int d = (e < EE) ? ei[EE + e] : (e - EE);
    atomicAdd(&g_deg[d], 1);
}

__global__ void k_scan1() {
    __shared__ int sm[SCAN_B];
    int t = threadIdx.x;
    int i = blockIdx.x * SCAN_B + t;
    int v = (i < NN) ? g_deg[i] : 0;
    sm[t] = v;
    __syncthreads();
    #pragma unroll
    for (int off = 1; off < SCAN_B; off <<= 1) {
        int xv = (t >= off) ? sm[t - off] : 0;
        __syncthreads();
        sm[t] += xv;
        __syncthreads();
    }
    if (i < NN) g_off[i] = sm[t];
    if (t == SCAN_B - 1) g_bsum[blockIdx.x] = sm[t];
}

__global__ void k_scan2() {
    if (threadIdx.x == 0) {
        int run = 0;
        for (int b = 0; b < NBLK; b++) {
            int t = g_bsum[b];
            g_bsum[b] = run;
            run += t;
        }
        g_off[NN] = run;
    }
}

__global__ void k_scan3() {
    int i = blockIdx.x * blockDim.x + threadIdx.x;
    if (i >= NN) return;
    int e = g_off[i] - g_deg[i] + g_bsum[i / SCAN_B];
    g_off[i] = e;
    g_cur[i] = e;
}

__global__ void k_scatter(const int* __restrict__ ei) {
    int e = blockIdx.x * blockDim.x + threadIdx.x;
    if (e >= ETOT) return;
    int s, d;
    if (e < EE) { s = ei[e]; d = ei[EE + e]; }
    else { s = d = e - EE; }
    int p = atomicAdd(&g_cur[d], 1);
    g_csr[p] = s;
}

// ---------------- double-buffered fp16 tensor-core GEMM + fused attn coeffs ------
// C[M,256] = A[M,K] @ B[K,256].  BN=64 == head width -> blockIdx.y == head.
// MODE 0: A = concat(x fp32, PE)  (layer 1)
// MODE 1: A = ELU(BN(hF fp32))    (layer 2; BN params computed in-kernel from sums)
template <int K, int MODE>
__global__ void k_gemm_tc(const float* __restrict__ Af,
                          const float* __restrict__ Bw,
                          __half* __restrict__ C, int M,
                          const float* __restrict__ x, const int* __restrict__ batch,
                          const float* __restrict__ Wpos, const float* __restrict__ bpos,
                          const float* __restrict__ a_src, const float* __restrict__ a_dst,
                          const float* __restrict__ bnsums,
                          const float* __restrict__ gamma, const float* __restrict__ beta) {
    const int BM = 128, BN = 64, BK = 32;
    const int LDAH = 40;             // halves per A row (32 + 8 pad)
    const int LDBH = 72;             // halves per B row (64 + 8 pad)
    const int LDB = BN + 4;          // float epilogue stride
    const int ATILE = BM * LDAH;     // 5120 halves
    const int BTILE = BK * LDBH;     // 2304 halves
    __shared__ __align__(16) char smraw[BM * LDB * 4];   // 34816 B; dbuf 29696 B + prm 2048 B
    float* smf = (float*)smraw;
    __half* base = (__half*)smraw;
    float* sprm = (float*)(smraw + 2 * (ATILE + BTILE) * 2);   // 512 floats

    int tid = threadIdx.x;
    int warp = tid >> 5;
    int wm = warp & 3;
    int wn = warp >> 2;
    int row0 = blockIdx.x * BM;
    int col0 = blockIdx.y * BN;

    int r = tid >> 1;                // A row 0..127
    int cbase = (tid & 1) * 16;      // A k-offset 0/16
    int kk = tid >> 3;               // B row 0..31
    int cc = (tid & 7) * 8;          // B col 0..56
    int gr = row0 + r;

    // MODE 1: BN scale/offset table in smem (one channel per thread)
    if (MODE == 1) {
        float mean = bnsums[tid] / (float)NN;
        float var = bnsums[HC + tid] / (float)NN - mean * mean;
        float inv = rsqrtf(var + 1e-5f);
        float sc = gamma[tid] * inv;
        sprm[tid] = sc;
        sprm[HC + tid] = beta[tid] - mean * sc;
    }

    wmma::fragment<wmma::accumulator, 16, 16, 16, float> acc[2][2];
    #pragma unroll
    for (int i = 0; i < 2; i++)
        #pragma unroll
        for (int j = 0; j < 2; j++) wmma::fill_fragment(acc[i][j], 0.f);

    float4 ra[4];
    float4 rb[2];

    const int NIT = (K + BK - 1) / BK;

    auto load_tile = [&](int k0) {
        bool peStage = (MODE == 0) && (k0 >= F_IN);
        if (!peStage) {
            const float* src = (MODE == 0) ? (x + (size_t)gr * F_IN + k0 + cbase)
                                           : (Af + (size_t)gr * K + k0 + cbase);
            #pragma unroll
            for (int v = 0; v < 4; v++)
                ra[v] = (gr < M) ? *(const float4*)(src + v * 4)
                                 : make_float4(0, 0, 0, 0);
        }
        #pragma unroll
        for (int v = 0; v < 2; v++) {
            int krow = k0 + kk;
            rb[v] = (krow < K) ? *(const float4*)&Bw[(size_t)krow * HC + col0 + cc + v * 4]
                               : make_float4(0, 0, 0, 0);
        }
    };

    auto store_tile = [&](int k0, int buf) {
        __half* As = base + buf * (ATILE + BTILE);
        __half* Bs = As + ATILE;
        __half* dst = &As[r * LDAH + cbase];
        if (MODE == 0 && k0 >= F_IN) {
            if (cbase == 0) {
                float p0 = 0.f, p1 = 0.f;
                if (gr < M) {
                    int b = batch[gr];
                    int g = g_gs[b];
                    int i = gr - g_starts[b];
                    int rowI = i / g;
                    int colI = i - rowI * g;
                    float denom = (float)(g - 1 > 1 ? g - 1 : 1);
                    p0 = (float)rowI / denom;
                    p1 = (float)colI / denom;
                }
                #pragma unroll
                for (int jj = 0; jj < 16; jj += 2) {
                    float v0 = (gr < M) ? (p0 * Wpos[jj] + p1 * Wpos[POS + jj] + bpos[jj]) : 0.f;
                    float v1 = (gr < M) ? (p0 * Wpos[jj + 1] + p1 * Wpos[POS + jj + 1] + bpos[jj + 1]) : 0.f;
                    *(__half2*)&dst[jj] = __floats2half2_rn(v0, v1);
                }
            } else {
                #pragma unroll
                for (int jj = 0; jj < 16; jj += 8)
                    *(float4*)&dst[jj] = make_float4(0, 0, 0, 0);
            }
        } else if (MODE == 1) {
            float* rf = (float*)ra;
            int ch0 = k0 + cbase;
            #pragma unroll
            for (int jj = 0; jj < 16; jj += 2) {
                float v0 = rf[jj]     * sprm[ch0 + jj]     + sprm[HC + ch0 + jj];
                float v1 = rf[jj + 1] * sprm[ch0 + jj + 1] + sprm[HC + ch0 + jj + 1];
                v0 = v0 > 0.f ? v0 : (__expf(v0) - 1.f);
                v1 = v1 > 0.f ? v1 : (__expf(v1) - 1.f);
                *(__half2*)&dst[jj] = __floats2half2_rn(v0, v1);
            }
        } else {
            #pragma unroll
            for (int v = 0; v < 4; v++) {
                *(__half2*)&dst[v * 4]     = __floats2half2_rn(ra[v].x, ra[v].y);
                *(__half2*)&dst[v * 4 + 2] = __floats2half2_rn(ra[v].z, ra[v].w);
            }
        }
        __half* d = &Bs[kk * LDBH + cc];
        *(__half2*)&d[0] = __floats2half2_rn(rb[0].x, rb[0].y);
        *(__half2*)&d[2] = __floats2half2_rn(rb[0].z, rb[0].w);
        *(__half2*)&d[4] = __floats2half2_rn(rb[1].x, rb[1].y);
        *(__half2*)&d[6] = __floats2half2_rn(rb[1].z, rb[1].w);
    };

    // prologue (sync after sprm init, before store_tile reads it)
    load_tile(0);
    if (MODE == 1) __syncthreads();
    store_tile(0, 0);
    __syncthreads();

    for (int it = 0; it < NIT; it++) {
        int cur = it & 1;
        if (it + 1 < NIT) load_tile((it + 1) * BK);

        __half* As = base + cur * (ATILE + BTILE);
        __half* Bs = As + ATILE;
        #pragma unroll
        for (int ks = 0; ks < BK; ks += 16) {
            wmma::fragment<wmma::matrix_a, 16, 16, 16, __half, wmma::row_major> af[2];
            wmma::fragment<wmma::matrix_b, 16, 16, 16, __half, wmma::row_major> bf[2];
            #pragma unroll
            for (int i = 0; i < 2; i++)
                wmma::load_matrix_sync(af[i], &As[(wm * 32 + i * 16) * LDAH + ks], LDAH);
            #pragma unroll
            for (int j = 0; j < 2; j++)
                wmma::load_matrix_sync(bf[j], &Bs[ks * LDBH + wn * 32 + j * 16], LDBH);
            #pragma unroll
            for (int i = 0; i < 2; i++)
                #pragma unroll
                for (int j = 0; j < 2; j++)
                    wmma::mma_sync(acc[i][j], af[i], bf[j], acc[i][j]);
        }

        if (it + 1 < NIT) store_tile((it + 1) * BK, cur ^ 1);
        __syncthreads();
    }

    // ---- epilogue: stage C tile in fp32 smem, fp16 writeout, attn coefficients ----
    #pragma unroll
    for (int i = 0; i < 2; i++)
        #pragma unroll
        for (int j = 0; j < 2; j++)
            wmma::store_matrix_sync(&smf[(wm * 32 + i * 16) * LDB + wn * 32 + j * 16],
                                    acc[i][j], LDB, wmma::mem_row_major);
    __syncthreads();

    for (int e = tid; e < BM * BN / 2; e += 256) {
        int rr = e >> 5;
        int c = (e & 31) * 2;
        int grr = row0 + rr;
        if (grr < M) {
            __half2 hv = __floats2half2_rn(smf[rr * LDB + c], smf[rr * LDB + c + 1]);
            *(__half2*)&C[(size_t)grr * HC + col0 + c] = hv;
        }
    }

    {
        int head = blockIdx.y;
        int halfc = (tid & 1) * 32;
        const float* av = a_src + head * 64;
        const float* dv = a_dst + head * 64;
        float ps = 0.f, pd = 0.f;
        #pragma unroll 8
        for (int k = 0; k < 32; k++) {
            float v = smf[r * LDB + halfc + k];
            ps += v * av[halfc + k];
            pd += v * dv[halfc + k];
        }
        ps += __shfl_xor_sync(0xFFFFFFFFu, ps, 1);
        pd += __shfl_xor_sync(0xFFFFFFFFu, pd, 1);
        if ((tid & 1) == 0 && gr < M) {
            g_as[gr * 4 + head] = ps;
            g_ad[gr * 4 + head] = pd;
        }
    }
}

// ---------------- softmax-aggregate (warp/node, fp16 h, unrolled MLP) + BN stats --
__global__ void k_agg(const __half* __restrict__ h, const float* __restrict__ bias,
                      float* __restrict__ out, float* __restrict__ bnsums) {
    int tid = threadIdx.x;
    int wp = tid >> 5;
    int lane = tid & 31;
    int node = blockIdx.x * 8 + wp;
    __shared__ float wsm[8][32][4];
    __shared__ int   ssm[8][32];
    __shared__ float ssum[HC];
    __shared__ float ssum2[HC];
    ssum[tid] = 0.f;
    ssum2[tid] = 0.f;
    __syncthreads();

    int beg = g_off[node], end = g_off[node + 1];
    float ad0 = g_ad[node * 4 + 0], ad1 = g_ad[node * 4 + 1];
    float ad2 = g_ad[node * 4 + 2], ad3 = g_ad[node * 4 + 3];

    float2 acc0 = {0.f, 0.f}, acc1 = {0.f, 0.f}, acc2 = {0.f, 0.f}, acc3 = {0.f, 0.f};
    float sw0 = 0.f, sw1 = 0.f, sw2 = 0.f, sw3 = 0.f;
    for (int base = beg; base < end; base += 32) {
        int j = base + lane;
        float w0 = 0.f, w1 = 0.f, w2 = 0.f, w3 = 0.f;
        int s = beg < end ? g_csr[(j < end) ? j : beg] : 0;
        if (j < end) {
            const float* as = &g_as[s * 4];
            float v0 = as[0] + ad0; v0 = v0 > 0.f ? v0 : 0.2f * v0; w0 = __expf(v0);
            float v1 = as[1] + ad1; v1 = v1 > 0.f ? v1 : 0.2f * v1; w1 = __expf(v1);
            float v2 = as[2] + ad2; v2 = v2 > 0.f ? v2 : 0.2f * v2; w2 = __expf(v2);
            float v3 = as[3] + ad3; v3 = v3 > 0.f ? v3 : 0.2f * v3; w3 = __expf(v3);
        }
        wsm[wp][lane][0] = w0; wsm[wp][lane][1] = w1;
        wsm[wp][lane][2] = w2; wsm[wp][lane][3] = w3;
        ssm[wp][lane] = s;
        sw0 += w0; sw1 += w1; sw2 += w2; sw3 += w3;
        __syncwarp();
        int cnt = end - base; if (cnt > 32) cnt = 32;
        int cnt4 = (cnt + 3) & ~3;
        for (int t = 0; t < cnt4; t += 4) {
            float2 f[4][4];
            float wv[4][4];
            #pragma unroll
            for (int u = 0; u < 4; u++) {
                int ss = ssm[wp][t + u];
                const __half2* hp = (const __half2*)(h + (size_t)ss * HC) + lane;
                f[u][0] = __half22float2(hp[0]);
                f[u][1] = __half22float2(hp[32]);
                f[u][2] = __half22float2(hp[64]);
                f[u][3] = __half22float2(hp[96]);
                wv[u][0] = wsm[wp][t + u][0];
                wv[u][1] = wsm[wp][t + u][1];
                wv[u][2] = wsm[wp][t + u][2];
                wv[u][3] = wsm[wp][t + u][3];
            }
            #pragma unroll
            for (int u = 0; u < 4; u++) {
                acc0.x += wv[u][0] * f[u][0].x; acc0.y += wv[u][0] * f[u][0].y;
                acc1.x += wv[u][1] * f[u][1].x; acc1.y += wv[u][1] * f[u][1].y;
                acc2.x += wv[u][2] * f[u][2].x; acc2.y += wv[u][2] * f[u][2].y;
                acc3.x += wv[u][3] * f[u][3].x; acc3.y += wv[u][3] * f[u][3].y;
            }
        }
        __syncwarp();
    }
    #pragma unroll
    for (int off = 16; off; off >>= 1) {
        sw0 += __shfl_xor_sync(0xFFFFFFFFu, sw0, off);
        sw1 += __shfl_xor_sync(0xFFFFFFFFu, sw1, off);
        sw2 += __shfl_xor_sync(0xFFFFFFFFu, sw2, off);
        sw3 += __shfl_xor_sync(0xFFFFFFFFu, sw3, off);
    }
    float i0 = 1.f / sw0, i1 = 1.f / sw1, i2 = 1.f / sw2, i3 = 1.f / sw3;
    int c0 = 2 * lane;
    float2 r0, r1, r2, r3;
    r0.x = acc0.x * i0 + bias[c0];        r0.y = acc0.y * i0 + bias[c0 + 1];
    r1.x = acc1.x * i1 + bias[c0 + 64];   r1.y = acc1.y * i1 + bias[c0 + 65];
    r2.x = acc2.x * i2 + bias[c0 + 128];  r2.y = acc2.y * i2 + bias[c0 + 129];
    r3.x = acc3.x * i3 + bias[c0 + 192];  r3.y = acc3.y * i3 + bias[c0 + 193];
    float* op = &out[(size_t)node * HC];
    *(float2*)&op[c0]       = r0;
    *(float2*)&op[c0 + 64]  = r1;
    *(float2*)&op[c0 + 128] = r2;
    *(float2*)&op[c0 + 192] = r3;
    atomicAdd(&ssum[c0], r0.x);        atomicAdd(&ssum[c0 + 1], r0.y);
    atomicAdd(&ssum[c0 + 64], r1.x);   atomicAdd(&ssum[c0 + 65], r1.y);
    atomicAdd(&ssum[c0 + 128], r2.x);  atomicAdd(&ssum[c0 + 129], r2.y);
    atomicAdd(&ssum[c0 + 192], r3.x);  atomicAdd(&ssum[c0 + 193], r3.y);
    atomicAdd(&ssum2[c0], r0.x * r0.x);        atomicAdd(&ssum2[c0 + 1], r0.y * r0.y);
    atomicAdd(&ssum2[c0 + 64], r1.x * r1.x);   atomicAdd(&ssum2[c0 + 65], r1.y * r1.y);
    atomicAdd(&ssum2[c0 + 128], r2.x * r2.x);  atomicAdd(&ssum2[c0 + 129], r2.y * r2.y);
    atomicAdd(&ssum2[c0 + 192], r3.x * r3.x);  atomicAdd(&ssum2[c0 + 193], r3.y * r3.y);
    __syncthreads();
    atomicAdd(&bnsums[tid], ssum[tid]);
    atomicAdd(&bnsums[HC + tid], ssum2[tid]);
}

// layer 2: BN finalize + BN+ELU + pool, all fused (no activation writeback)
__global__ void k_bn_elu_pool(const float* __restrict__ x, const float* __restrict__ sums,
                              const float* __restrict__ gamma, const float* __restrict__ beta,
                              const int* __restrict__ batch) {
    int ch = threadIdx.x;
    float mean = sums[ch] / (float)NN;
    float var = sums[HC + ch] / (float)NN - mean * mean;
    float inv = rsqrtf(var + 1e-5f);
    float sc = gamma[ch] * inv;
    float of = beta[ch] - mean * sc;
    int r0 = blockIdx.x * 128;
    int rend = r0 + 128; if (rend > NN) rend = NN;
    float acc = 0.f;
    int gcur = batch[r0];
    for (int r = r0; r < rend; r++) {
        int g = batch[r];
        if (g != gcur) {
            atomicAdd(&g_pool[gcur * HC + ch], acc);
            acc = 0.f;
            gcur = g;
        }
        float v = x[(size_t)r * HC + ch] * sc + of;
        acc += (v > 0.f ? v : (__expf(v) - 1.f));
    }
    atomicAdd(&g_pool[gcur * HC + ch], acc);
}

__global__ void k_fc(const float* __restrict__ Wfc, const float* __restrict__ bfc,
                     float* __restrict__ out) {
    int g = blockIdx.x, o = threadIdx.x;
    __shared__ float ps[HC];
    float invc = 1.f / (float)g_counts[g];
    for (int c = o; c < HC; c += OUT_DIM) ps[c] = g_pool[g * HC + c] * invc;
    __syncthreads();
    float acc = bfc[o];
    #pragma unroll 8
    for (int c = 0; c < HC; c++) acc += ps[c] * Wfc[c * OUT_DIM + o];
    out[g * OUT_DIM + o] = acc;
}

// ---------------- launch ----------------
extern "C" void kernel_launch(void* const* d_in, const int* in_sizes, int n_in,
                              void* d_out, int out_size) {
    const float* x       = (const float*)d_in[0];
    const int*   ei      = (const int*)d_in[1];
    const int*   batch   = (const int*)d_in[2];
    const float* W_pos   = (const float*)d_in[3];
    const float* b_pos   = (const float*)d_in[4];
    const float* W1      = (const float*)d_in[5];
    const float* a_src1  = (const float*)d_in[6];
    const float* a_dst1  = (const float*)d_in[7];
    const float* b1      = (const float*)d_in[8];
    const float* gamma1  = (const float*)d_in[9];
    const float* beta1   = (const float*)d_in[10];
    const float* W2      = (const float*)d_in[11];
    const float* a_src2  = (const float*)d_in[12];
    const float* a_dst2  = (const float*)d_in[13];
    const float* b2      = (const float*)d_in[14];
    const float* gamma2  = (const float*)d_in[15];
    const float* beta2   = (const float*)d_in[16];
    const float* W_fc    = (const float*)d_in[17];
    const float* b_fc    = (const float*)d_in[18];
    float* out = (float*)d_out;

    __half* hH;
    float *hF, *bn1, *bn2;
    cudaGetSymbolAddress((void**)&hH, g_hH);
    cudaGetSymbolAddress((void**)&hF, g_hF);
    cudaGetSymbolAddress((void**)&bn1, g_bn1);
    cudaGetSymbolAddress((void**)&bn2, g_bn2);

    // ---- common zero pass ----
    k_zero<<<256, 256>>>();

    // ---- fork: CSR build on side stream, concurrent with meta + GEMM1 ----
    cudaEventRecord(g_evFork, 0);
    cudaStreamWaitEvent(g_s2, g_evFork, 0);

    k_degree<<<(ETOT + 255) / 256, 256, 0, g_s2>>>(ei);
    k_scan1<<<NBLK, SCAN_B, 0, g_s2>>>();
    k_scan2<<<1, 32, 0, g_s2>>>();
    k_scan3<<<(NN + 255) / 256, 256, 0, g_s2>>>();
    k_scatter<<<(ETOT + 255) / 256, 256, 0, g_s2>>>(ei);

    // main stream: graph meta + layer-1 GEMM (PE + attn fused)
    k_counts<<<(NN + 255) / 256, 256>>>(batch);
    k_graph_meta<<<1, 32>>>();

    dim3 gg((NN + 127) / 128, HC / 64);
    k_gemm_tc<ENH, 0><<<gg, 256>>>(nullptr, W1, hH, NN,
                                   x, batch, W_pos, b_pos, a_src1, a_dst1,
                                   nullptr, nullptr, nullptr);

    // ---- join: agg needs the CSR ----
    cudaEventRecord(g_evJoin, g_s2);
    cudaStreamWaitEvent(0, g_evJoin, 0);

    k_agg<<<NN / 8, 256>>>(hH, b1, hF, bn1);

    // layer 2: BN+ELU fused into GEMM2 A-path (BN params from bn1 sums, in-kernel)
    k_gemm_tc<HC, 1><<<gg, 256>>>(hF, W2, hH, NN,
                                  nullptr, nullptr, nullptr, nullptr, a_src2, a_dst2,
                                  bn1, gamma1, beta1);
    k_agg<<<NN / 8, 256>>>(hH, b2, hF, bn2);

    // fused BN finalize + BN+ELU + pool
    k_bn_elu_pool<<<(NN + 127) / 128, 256>>>(hF, bn2, gamma2, beta2, batch);
    k_fc<<<BB, OUT_DIM>>>(W_fc, b_fc, out);
}

// round 11
// speedup vs baseline: 1.0446x; 1.0446x over previous
#include <cuda_runtime.h>
#include <cuda_fp16.h>
#include <math.h>
#include <mma.h>

using namespace nvcuda;

#define NN 50000
#define EE 800000
#define ETOT (EE + NN)
#define BB 64
#define F_IN 128
#define POS 16
#define ENH 144
#define HC 256
#define OUT_DIM 128
#define SCAN_B 1024
#define NBLK ((NN + SCAN_B - 1) / SCAN_B)   // 49

// ---------------- scratch (device globals; no allocation allowed) ----------------
__device__ __half g_hH[(size_t)NN * HC];    // GEMM output (feeds aggregation only)
__device__ __half g_xH[(size_t)NN * HC];    // BN+ELU output (feeds GEMM2 A)
__device__ float  g_hF[(size_t)NN * HC];    // agg output / BN stats source
__device__ float g_as[NN * 4];
__device__ float g_ad[NN * 4];
__device__ int   g_deg[NN];
__device__ int   g_off[NN + 1];
__device__ int   g_cur[NN];
__device__ int   g_csr[ETOT];
__device__ int   g_bsum[NBLK];
__device__ int   g_counts[BB];
__device__ int   g_starts[BB];
__device__ int   g_gs[BB];
__device__ float g_bn1[512];
__device__ float g_bn2[512];
__device__ float g_pool[BB * HC];

// ---------------- side stream + events (host-side resources, created once) -------
static cudaStream_t g_s2 = nullptr;
static cudaEvent_t  g_evFork = nullptr, g_evJoin = nullptr;
static struct StreamInit {
    StreamInit() {
        cudaStreamCreateWithFlags(&g_s2, cudaStreamNonBlocking);
        cudaEventCreateWithFlags(&g_evFork, cudaEventDisableTiming);
        cudaEventCreateWithFlags(&g_evJoin, cudaEventDisableTiming);
    }
} g_streamInit;

// ---------------- zero scratch ----------------
__global__ void k_zero() {
    int stride = gridDim.x * blockDim.x;
    int i = blockIdx.x * blockDim.x + threadIdx.x;
    for (int j = i; j < NN; j += stride) g_deg[j] = 0;
    for (int j = i; j < BB; j += stride) g_counts[j] = 0;
    for (int j = i; j < 512; j += stride) { g_bn1[j] = 0.f; g_bn2[j] = 0.f; }
    for (int j = i; j < BB * HC; j += stride) g_pool[j] = 0.f;
}

// ---------------- graph counts ----------------
__global__ void k_counts(const int* __restrict__ batch) {
    __shared__ int sm[BB];
    int t = threadIdx.x;
    if (t < BB) sm[t] = 0;
    __syncthreads();
    int i = blockIdx.x * blockDim.x + t;
    if (i < NN) atomicAdd(&sm[batch[i]], 1);
    __syncthreads();
    if (t < BB && sm[t]) atomicAdd(&g_counts[t], sm[t]);
}

__global__ void k_graph_meta() {
    if (threadIdx.x == 0 && blockIdx.x == 0) {
        int acc = 0;
        for (int b = 0; b < BB; b++) {
            int c = g_counts[b];
            g_starts[b] = acc;
            acc += c;
            g_gs[b] = (int)ceilf(sqrtf((float)c));
        }
    }
}

// ---------------- CSR build ----------------
__global__ void k_degree(const int* __restrict__ ei) {
    int e = blockIdx.x * blockDim.x + threadIdx.x;
    if (e >= ETOT) return;
    int d = (e < EE) ? ei[EE + e] : (e - EE);
    atomicAdd(&g_deg[d], 1);
}

__global__ void k_scan1() {
    __shared__ int sm[SCAN_B];
    int t = threadIdx.x;
    int i = blockIdx.x * SCAN_B + t;
    int v = (i < NN) ? g_deg[i] : 0;
    sm[t] = v;
    __syncthreads();
    #pragma unroll
    for (int off = 1; off < SCAN_B; off <<= 1) {
        int xv = (t >= off) ? sm[t - off] : 0;
        __syncthreads();
        sm[t] += xv;
        __syncthreads();
    }
    if (i < NN) g_off[i] = sm[t];
    if (t == SCAN_B - 1) g_bsum[blockIdx.x] = sm[t];
}

__global__ void k_scan2() {
    if (threadIdx.x == 0) {
        int run = 0;
        for (int b = 0; b < NBLK; b++) {
            int t = g_bsum[b];
            g_bsum[b] = run;
            run += t;
        }
        g_off[NN] = run;
    }
}

__global__ void k_scan3() {
    int i = blockIdx.x * blockDim.x + threadIdx.x;
    if (i >= NN) return;
    int e = g_off[i] - g_deg[i] + g_bsum[i / SCAN_B];
    g_off[i] = e;
    g_cur[i] = e;
}

__global__ void k_scatter(const int* __restrict__ ei) {
    int e = blockIdx.x * blockDim.x + threadIdx.x;
    if (e >= ETOT) return;
    int s, d;
    if (e < EE) { s = ei[e]; d = ei[EE + e]; }
    else { s = d = e - EE; }
    int p = atomicAdd(&g_cur[d], 1);
    g_csr[p] = s;
}

// ---------------- double-buffered fp16 tensor-core GEMM + fused attn coeffs ------
// C[M,256] = A[M,K] @ B[K,256].  BN=64 == head width -> blockIdx.y == head.
template <int K, bool FUSE_PE, bool A_HALF>
__global__ void k_gemm_tc(const __half* __restrict__ Ah,
                          const float* __restrict__ Bw,
                          __half* __restrict__ C, int M,
                          const float* __restrict__ x, const int* __restrict__ batch,
                          const float* __restrict__ Wpos, const float* __restrict__ bpos,
                          const float* __restrict__ a_src, const float* __restrict__ a_dst) {
    const int BM = 128, BN = 64, BK = 32;
    const int LDAH = 40;             // halves per A row (32 + 8 pad)
    const int LDBH = 72;             // halves per B row (64 + 8 pad)
    const int LDB = BN + 4;          // float epilogue stride
    const int ATILE = BM * LDAH;     // 5120 halves
    const int BTILE = BK * LDBH;     // 2304 halves
    __shared__ __align__(16) char smraw[BM * LDB * 4];   // 34816 B; dbuf uses 29696 B
    float* smf = (float*)smraw;
    __half* base = (__half*)smraw;

    int tid = threadIdx.x;
    int warp = tid >> 5;
    int wm = warp & 3;
    int wn = warp >> 2;
    int row0 = blockIdx.x * BM;
    int col0 = blockIdx.y * BN;

    int r = tid >> 1;                // A row 0..127
    int cbase = (tid & 1) * 16;      // A k-offset 0/16
    int kk = tid >> 3;               // B row 0..31
    int cc = (tid & 7) * 8;          // B col 0..56
    int gr = row0 + r;

    wmma::fragment<wmma::accumulator, 16, 16, 16, float> acc[2][2];
    #pragma unroll
    for (int i = 0; i < 2; i++)
        #pragma unroll
        for (int j = 0; j < 2; j++) wmma::fill_fragment(acc[i][j], 0.f);

    float4 ra[4];
    float4 rb[2];

    const int NIT = (K + BK - 1) / BK;

    auto load_tile = [&](int k0) {
        bool peStage = FUSE_PE && (k0 >= F_IN);
        if (!peStage) {
            if (A_HALF) {
                const float4* src = (const float4*)(Ah + (size_t)gr * K + k0 + cbase);
                if (gr < M) { ra[0] = src[0]; ra[1] = src[1]; }
                else { ra[0] = make_float4(0, 0, 0, 0); ra[1] = ra[0]; }
            } else {
                const float* src = x + (size_t)gr * F_IN + k0 + cbase;
                #pragma unroll
                for (int v = 0; v < 4; v++)
                    ra[v] = (gr < M) ? *(const float4*)(src + v * 4)
                                     : make_float4(0, 0, 0, 0);
            }
        }
        #pragma unroll
        for (int v = 0; v < 2; v++) {
            int krow = k0 + kk;
            rb[v] = (krow < K) ? *(const float4*)&Bw[(size_t)krow * HC + col0 + cc + v * 4]
                               : make_float4(0, 0, 0, 0);
        }
    };

    auto store_tile = [&](int k0, int buf) {
        __half* As = base + buf * (ATILE + BTILE);
        __half* Bs = As + ATILE;
        __half* dst = &As[r * LDAH + cbase];
        if (FUSE_PE && k0 >= F_IN) {
            if (cbase == 0) {
                float p0 = 0.f, p1 = 0.f;
                if (gr < M) {
                    int b = batch[gr];
                    int g = g_gs[b];
                    int i = gr - g_starts[b];
                    int rowI = i / g;
                    int colI = i - rowI * g;
                    float denom = (float)(g - 1 > 1 ? g - 1 : 1);
                    p0 = (float)rowI / denom;
                    p1 = (float)colI / denom;
                }
                #pragma unroll
                for (int jj = 0; jj < 16; jj += 2) {
                    float v0 = (gr < M) ? (p0 * Wpos[jj] + p1 * Wpos[POS + jj] + bpos[jj]) : 0.f;
                    float v1 = (gr < M) ? (p0 * Wpos[jj + 1] + p1 * Wpos[POS + jj + 1] + bpos[jj + 1]) : 0.f;
                    *(__half2*)&dst[jj] = __floats2half2_rn(v0, v1);
                }
            } else {
                #pragma unroll
                for (int jj = 0; jj < 16; jj += 8)
                    *(float4*)&dst[jj] = make_float4(0, 0, 0, 0);
            }
        } else if (A_HALF) {
            *(float4*)&dst[0] = ra[0];
            *(float4*)&dst[8] = ra[1];
        } else {
            #pragma unroll
            for (int v = 0; v < 4; v++) {
                *(__half2*)&dst[v * 4]     = __floats2half2_rn(ra[v].x, ra[v].y);
                *(__half2*)&dst[v * 4 + 2] = __floats2half2_rn(ra[v].z, ra[v].w);
            }
        }
        __half* d = &Bs[kk * LDBH + cc];
        *(__half2*)&d[0] = __floats2half2_rn(rb[0].x, rb[0].y);
        *(__half2*)&d[2] = __floats2half2_rn(rb[0].z, rb[0].w);
        *(__half2*)&d[4] = __floats2half2_rn(rb[1].x, rb[1].y);
        *(__half2*)&d[6] = __floats2half2_rn(rb[1].z, rb[1].w);
    };

    // prologue
    load_tile(0);
    store_tile(0, 0);
    __syncthreads();

    for (int it = 0; it < NIT; it++) {
        int cur = it & 1;
        if (it + 1 < NIT) load_tile((it + 1) * BK);

        __half* As = base + cur * (ATILE + BTILE);
        __half* Bs = As + ATILE;
        #pragma unroll
        for (int ks = 0; ks < BK; ks += 16) {
            wmma::fragment<wmma::matrix_a, 16, 16, 16, __half, wmma::row_major> af[2];
            wmma::fragment<wmma::matrix_b, 16, 16, 16, __half, wmma::row_major> bf[2];
            #pragma unroll
            for (int i = 0; i < 2; i++)
                wmma::load_matrix_sync(af[i], &As[(wm * 32 + i * 16) * LDAH + ks], LDAH);
            #pragma unroll
            for (int j = 0; j < 2; j++)
                wmma::load_matrix_sync(bf[j], &Bs[ks * LDBH + wn * 32 + j * 16], LDBH);
            #pragma unroll
            for (int i = 0; i < 2; i++)
                #pragma unroll
                for (int j = 0; j < 2; j++)
                    wmma::mma_sync(acc[i][j], af[i], bf[j], acc[i][j]);
        }

        if (it + 1 < NIT) store_tile((it + 1) * BK, cur ^ 1);
        __syncthreads();
    }

    // ---- epilogue: stage C tile in fp32 smem, fp16 writeout, attn coefficients ----
    #pragma unroll
    for (int i = 0; i < 2; i++)
        #pragma unroll
        for (int j = 0; j < 2; j++)
            wmma::store_matrix_sync(&smf[(wm * 32 + i * 16) * LDB + wn * 32 + j * 16],
                                    acc[i][j], LDB, wmma::mem_row_major);
    __syncthreads();

    for (int e = tid; e < BM * BN / 2; e += 256) {
        int rr = e >> 5;
        int c = (e & 31) * 2;
        int grr = row0 + rr;
        if (grr < M) {
            __half2 hv = __floats2half2_rn(smf[rr * LDB + c], smf[rr * LDB + c + 1]);
            *(__half2*)&C[(size_t)grr * HC + col0 + c] = hv;
        }
    }

    {
        int head = blockIdx.y;
        int halfc = (tid & 1) * 32;
        const float* av = a_src + head * 64;
        const float* dv = a_dst + head * 64;
        float ps = 0.f, pd = 0.f;
        #pragma unroll 8
        for (int k = 0; k < 32; k++) {
            float v = smf[r * LDB + halfc + k];
            ps += v * av[halfc + k];
            pd += v * dv[halfc + k];
        }
        ps += __shfl_xor_sync(0xFFFFFFFFu, ps, 1);
        pd += __shfl_xor_sync(0xFFFFFFFFu, pd, 1);
        if ((tid & 1) == 0 && gr < M) {
            g_as[gr * 4 + head] = ps;
            g_ad[gr * 4 + head] = pd;
        }
    }
}

// ---------------- softmax-aggregate (warp/node, fp16 h, unrolled MLP) + BN stats --
__global__ void k_agg(const __half* __restrict__ h, const float* __restrict__ bias,
                      float* __restrict__ out, float* __restrict__ bnsums) {
    int tid = threadIdx.x;
    int wp = tid >> 5;
    int lane = tid & 31;
    int node = blockIdx.x * 8 + wp;
    __shared__ float wsm[8][32][4];
    __shared__ int   ssm[8][32];
    __shared__ float ssum[HC];
    __shared__ float ssum2[HC];
    ssum[tid] = 0.f;
    ssum2[tid] = 0.f;
    __syncthreads();

    int beg = g_off[node], end = g_off[node + 1];
    float ad0 = g_ad[node * 4 + 0], ad1 = g_ad[node * 4 + 1];
    float ad2 = g_ad[node * 4 + 2], ad3 = g_ad[node * 4 + 3];

    float2 acc0 = {0.f, 0.f}, acc1 = {0.f, 0.f}, acc2 = {0.f, 0.f}, acc3 = {0.f, 0.f};
    float sw0 = 0.f, sw1 = 0.f, sw2 = 0.f, sw3 = 0.f;
    for (int base = beg; base < end; base += 32) {
        int j = base + lane;
        float w0 = 0.f, w1 = 0.f, w2 = 0.f, w3 = 0.f;
        int s = beg < end ? g_csr[(j < end) ? j : beg] : 0;
        if (j < end) {
            const float* as = &g_as[s * 4];
            float v0 = as[0] + ad0; v0 = v0 > 0.f ? v0 : 0.2f * v0; w0 = __expf(v0);
            float v1 = as[1] + ad1; v1 = v1 > 0.f ? v1 : 0.2f * v1; w1 = __expf(v1);
            float v2 = as[2] + ad2; v2 = v2 > 0.f ? v2 : 0.2f * v2; w2 = __expf(v2);
            float v3 = as[3] + ad3; v3 = v3 > 0.f ? v3 : 0.2f * v3; w3 = __expf(v3);
        }
        wsm[wp][lane][0] = w0; wsm[wp][lane][1] = w1;
        wsm[wp][lane][2] = w2; wsm[wp][lane][3] = w3;
        ssm[wp][lane] = s;
        sw0 += w0; sw1 += w1; sw2 += w2; sw3 += w3;
        __syncwarp();
        int cnt = end - base; if (cnt > 32) cnt = 32;
        int cnt4 = (cnt + 3) & ~3;
        for (int t = 0; t < cnt4; t += 4) {
            float2 f[4][4];
            float wv[4][4];
            #pragma unroll
            for (int u = 0; u < 4; u++) {
                int ss = ssm[wp][t + u];
                const __half2* hp = (const __half2*)(h + (size_t)ss * HC) + lane;
                f[u][0] = __half22float2(hp[0]);
                f[u][1] = __half22float2(hp[32]);
                f[u][2] = __half22float2(hp[64]);
                f[u][3] = __half22float2(hp[96]);
                wv[u][0] = wsm[wp][t + u][0];
                wv[u][1] = wsm[wp][t + u][1];
                wv[u][2] = wsm[wp][t + u][2];
                wv[u][3] = wsm[wp][t + u][3];
            }
            #pragma unroll
            for (int u = 0; u < 4; u++) {
                acc0.x += wv[u][0] * f[u][0].x; acc0.y += wv[u][0] * f[u][0].y;
                acc1.x += wv[u][1] * f[u][1].x; acc1.y += wv[u][1] * f[u][1].y;
                acc2.x += wv[u][2] * f[u][2].x; acc2.y += wv[u][2] * f[u][2].y;
                acc3.x += wv[u][3] * f[u][3].x; acc3.y += wv[u][3] * f[u][3].y;
            }
        }
        __syncwarp();
    }
    #pragma unroll
    for (int off = 16; off; off >>= 1) {
        sw0 += __shfl_xor_sync(0xFFFFFFFFu, sw0, off);
        sw1 += __shfl_xor_sync(0xFFFFFFFFu, sw1, off);
        sw2 += __shfl_xor_sync(0xFFFFFFFFu, sw2, off);
        sw3 += __shfl_xor_sync(0xFFFFFFFFu, sw3, off);
    }
    float i0 = 1.f / sw0, i1 = 1.f / sw1, i2 = 1.f / sw2, i3 = 1.f / sw3;
    int c0 = 2 * lane;
    float2 r0, r1, r2, r3;
    r0.x = acc0.x * i0 + bias[c0];        r0.y = acc0.y * i0 + bias[c0 + 1];
    r1.x = acc1.x * i1 + bias[c0 + 64];   r1.y = acc1.y * i1 + bias[c0 + 65];
    r2.x = acc2.x * i2 + bias[c0 + 128];  r2.y = acc2.y * i2 + bias[c0 + 129];
    r3.x = acc3.x * i3 + bias[c0 + 192];  r3.y = acc3.y * i3 + bias[c0 + 193];
    float* op = &out[(size_t)node * HC];
    *(float2*)&op[c0]       = r0;
    *(float2*)&op[c0 + 64]  = r1;
    *(float2*)&op[c0 + 128] = r2;
    *(float2*)&op[c0 + 192] = r3;
    atomicAdd(&ssum[c0], r0.x);        atomicAdd(&ssum[c0 + 1], r0.y);
    atomicAdd(&ssum[c0 + 64], r1.x);   atomicAdd(&ssum[c0 + 65], r1.y);
    atomicAdd(&ssum[c0 + 128], r2.x);  atomicAdd(&ssum[c0 + 129], r2.y);
    atomicAdd(&ssum[c0 + 192], r3.x);  atomicAdd(&ssum[c0 + 193], r3.y);
    atomicAdd(&ssum2[c0], r0.x * r0.x);        atomicAdd(&ssum2[c0 + 1], r0.y * r0.y);
    atomicAdd(&ssum2[c0 + 64], r1.x * r1.x);   atomicAdd(&ssum2[c0 + 65], r1.y * r1.y);
    atomicAdd(&ssum2[c0 + 128], r2.x * r2.x);  atomicAdd(&ssum2[c0 + 129], r2.y * r2.y);
    atomicAdd(&ssum2[c0 + 192], r3.x * r3.x);  atomicAdd(&ssum2[c0 + 193], r3.y * r3.y);
    __syncthreads();
    atomicAdd(&bnsums[tid], ssum[tid]);
    atomicAdd(&bnsums[HC + tid], ssum2[tid]);
}

// BN finalize + BN+ELU fused: fp32 in -> fp16 out (feeds GEMM2 A only)
__global__ void k_bn_elu(const float* __restrict__ x, const float* __restrict__ sums,
                         const float* __restrict__ gamma, const float* __restrict__ beta,
                         __half* __restrict__ xo) {
    long i4 = (long)blockIdx.x * blockDim.x + threadIdx.x;
    if (i4 >= (long)NN * HC / 4) return;
    int ch = (int)(i4 & (HC / 4 - 1)) * 4;
    // inline BN params for the 4 channels (broadcast loads, L1-resident)
    float4 sm = *(const float4*)&sums[ch];
    float4 sq = *(const float4*)&sums[HC + ch];
    float4 ga = *(const float4*)&gamma[ch];
    float4 be = *(const float4*)&beta[ch];
    const float invN = 1.f / (float)NN;
    float m0 = sm.x * invN, m1 = sm.y * invN, m2 = sm.z * invN, m3 = sm.w * invN;
    float s0 = ga.x * rsqrtf(sq.x * invN - m0 * m0 + 1e-5f);
    float s1 = ga.y * rsqrtf(sq.y * invN - m1 * m1 + 1e-5f);
    float s2 = ga.z * rsqrtf(sq.z * invN - m2 * m2 + 1e-5f);
    float s3 = ga.w * rsqrtf(sq.w * invN - m3 * m3 + 1e-5f);
    float o0 = be.x - m0 * s0, o1 = be.y - m1 * s1, o2 = be.z - m2 * s2, o3 = be.w - m3 * s3;

    float4 v = *(const float4*)&x[i4 * 4];
    v.x = v.x * s0 + o0; v.x = v.x > 0.f ? v.x : (__expf(v.x) - 1.f);
    v.y = v.y * s1 + o1; v.y = v.y > 0.f ? v.y : (__expf(v.y) - 1.f);
    v.z = v.z * s2 + o2; v.z = v.z > 0.f ? v.z : (__expf(v.z) - 1.f);
    v.w = v.w * s3 + o3; v.w = v.w > 0.f ? v.w : (__expf(v.w) - 1.f);
    __half2 h0 = __floats2half2_rn(v.x, v.y);
    __half2 h1 = __floats2half2_rn(v.z, v.w);
    *(__half2*)&xo[i4 * 4]     = h0;
    *(__half2*)&xo[i4 * 4 + 2] = h1;
}

// layer 2: BN finalize + BN+ELU + pool, all fused (no activation writeback)
__global__ void k_bn_elu_pool(const float* __restrict__ x, const float* __restrict__ sums,
                              const float* __restrict__ gamma, const float* __restrict__ beta,
                              const int* __restrict__ batch) {
    int ch = threadIdx.x;
    float mean = sums[ch] / (float)NN;
    float var = sums[HC + ch] / (float)NN - mean * mean;
    float inv = rsqrtf(var + 1e-5f);
    float sc = gamma[ch] * inv;
    float of = beta[ch] - mean * sc;
    int r0 = blockIdx.x * 128;
    int rend = r0 + 128; if (rend > NN) rend = NN;
    float acc = 0.f;
    int gcur = batch[r0];
    for (int r = r0; r < rend; r++) {
        int g = batch[r];
        if (g != gcur) {
            atomicAdd(&g_pool[gcur * HC + ch], acc);
            acc = 0.f;
            gcur = g;
        }
        float v = x[(size_t)r * HC + ch] * sc + of;
        acc += (v > 0.f ? v : (__expf(v) - 1.f));
    }
    atomicAdd(&g_pool[gcur * HC + ch], acc);
}

__global__ void k_fc(const float* __restrict__ Wfc, const float* __restrict__ bfc,
                     float* __restrict__ out) {
    int g = blockIdx.x, o = threadIdx.x;
    __shared__ float ps[HC];
    float invc = 1.f / (float)g_counts[g];
    for (int c = o; c < HC; c += OUT_DIM) ps[c] = g_pool[g * HC + c] * invc;
    __syncthreads();
    float acc = bfc[o];
    #pragma unroll 8
    for (int c = 0; c < HC; c++) acc += ps[c] * Wfc[c * OUT_DIM + o];
    out[g * OUT_DIM + o] = acc;
}

// ---------------- launch ----------------
extern "C" void kernel_launch(void* const* d_in, const int* in_sizes, int n_in,
                              void* d_out, int out_size) {
    const float* x       = (const float*)d_in[0];
    const int*   ei      = (const int*)d_in[1];
    const int*   batch   = (const int*)d_in[2];
    const float* W_pos   = (const float*)d_in[3];
    const float* b_pos   = (const float*)d_in[4];
    const float* W1      = (const float*)d_in[5];
    const float* a_src1  = (const float*)d_in[6];
    const float* a_dst1  = (const float*)d_in[7];
    const float* b1      = (const float*)d_in[8];
    const float* gamma1  = (const float*)d_in[9];
    const float* beta1   = (const float*)d_in[10];
    const float* W2      = (const float*)d_in[11];
    const float* a_src2  = (const float*)d_in[12];
    const float* a_dst2  = (const float*)d_in[13];
    const float* b2      = (const float*)d_in[14];
    const float* gamma2  = (const float*)d_in[15];
    const float* beta2   = (const float*)d_in[16];
    const float* W_fc    = (const float*)d_in[17];
    const float* b_fc    = (const float*)d_in[18];
    float* out = (float*)d_out;

    __half *hH, *xH;
    float *hF, *bn1, *bn2;
    cudaGetSymbolAddress((void**)&hH, g_hH);
    cudaGetSymbolAddress((void**)&xH, g_xH);
    cudaGetSymbolAddress((void**)&hF, g_hF);
    cudaGetSymbolAddress((void**)&bn1, g_bn1);
    cudaGetSymbolAddress((void**)&bn2, g_bn2);

    // ---- common zero pass ----
    k_zero<<<256, 256>>>();

    // ---- fork: CSR build on side stream, concurrent with meta + GEMM1 ----
    cudaEventRecord(g_evFork, 0);
    cudaStreamWaitEvent(g_s2, g_evFork, 0);

    k_degree<<<(ETOT + 255) / 256, 256, 0, g_s2>>>(ei);
    k_scan1<<<NBLK, SCAN_B, 0, g_s2>>>();
    k_scan2<<<1, 32, 0, g_s2>>>();
    k_scan3<<<(NN + 255) / 256, 256, 0, g_s2>>>();
    k_scatter<<<(ETOT + 255) / 256, 256, 0, g_s2>>>(ei);

    // main stream: graph meta + layer-1 GEMM (PE + attn fused)
    k_counts<<<(NN + 255) / 256, 256>>>(batch);
    k_graph_meta<<<1, 32>>>();

    dim3 gg((NN + 127) / 128, HC / 64);
    k_gemm_tc<ENH, true, false><<<gg, 256>>>(nullptr, W1, hH, NN,
                                             x, batch, W_pos, b_pos, a_src1, a_dst1);

    // ---- join: agg needs the CSR ----
    cudaEventRecord(g_evJoin, g_s2);
    cudaStreamWaitEvent(0, g_evJoin, 0);

    k_agg<<<NN / 8, 256>>>(hH, b1, hF, bn1);
    k_bn_elu<<<(int)(((long)NN * HC / 4 + 255) / 256), 256>>>(hF, bn1, gamma1, beta1, xH);

    // layer 2 (fp16 A operand)
    k_gemm_tc<HC, false, true><<<gg, 256>>>(xH, W2, hH, NN,
                                            nullptr, nullptr, nullptr, nullptr, a_src2, a_dst2);
    k_agg<<<NN / 8, 256>>>(hH, b2, hF, bn2);

    // fused BN finalize + BN+ELU + pool
    k_bn_elu_pool<<<(NN + 127) / 128, 256>>>(hF, bn2, gamma2, beta2, batch);
    k_fc<<<BB, OUT_DIM>>>(W_fc, b_fc, out);
}